// round 5
// baseline (speedup 1.0000x reference)
#include <cuda_runtime.h>
#include <stdint.h>

#define N_   32
#define H_   56
#define W_   56
#define C_   256
#define HP   58
#define WP   58
#define COUT 256
#define KTOT 2304
#define NPIXP (N_ * HP * WP)

#define ASTRIDE 80            /* smem row stride bytes (conflict-free) */
#define A_BYTES (128 * ASTRIDE)   /* 10240 */
#define B_BYTES (256 * ASTRIDE)   /* 20480 */
#define STAGE   (A_BYTES + B_BYTES) /* 30720 */
#define SM_KSC  (2 * STAGE)       /* 61440: 128 floats of ksc */
#define SMEM_SZ (SM_KSC + 512 + 128)
#define NCHUNK  36

// ---------------- device scratch ----------------
__device__ int8_t g_x8[(size_t)NPIXP * C_ + 4096];  // padded sign(x) as +/-1 s8
__device__ int8_t g_k8[(size_t)COUT * KTOT];        // sign(k) [cout][k]
__device__ float  g_kpart[72 * COUT];
__device__ float  g_alpha[COUT];
__device__ float  g_betap[NPIXP];

// ---------------- PTX helpers ----------------
__device__ __forceinline__ uint32_t smem_u32(const void* p) {
    uint32_t a;
    asm("{ .reg .u64 t; cvta.to.shared.u64 t, %1; cvt.u32.u64 %0, t; }"
        : "=r"(a) : "l"(p));
    return a;
}
#define CP_ASYNC16(dst, src) \
    asm volatile("cp.async.cg.shared.global [%0], [%1], 16;" \
                 :: "r"(dst), "l"(src) : "memory")
#define CP_COMMIT() asm volatile("cp.async.commit_group;" ::: "memory")
#define CP_WAIT1()  asm volatile("cp.async.wait_group 1;" ::: "memory")
#define CP_WAIT0()  asm volatile("cp.async.wait_group 0;" ::: "memory")
#define LDSM_X4(r0, r1, r2, r3, a) \
    asm volatile("ldmatrix.sync.aligned.m8n8.x4.shared.b16 {%0,%1,%2,%3}, [%4];" \
                 : "=r"(r0), "=r"(r1), "=r"(r2), "=r"(r3) : "r"(a))
#define LDSM_X2(r0, r1, a) \
    asm volatile("ldmatrix.sync.aligned.m8n8.x2.shared.b16 {%0,%1}, [%2];" \
                 : "=r"(r0), "=r"(r1) : "r"(a))
#define IMMA(d, a0, a1, a2, a3, b0, b1) \
    asm volatile("mma.sync.aligned.m16n8k32.row.col.s32.s8.s8.s32 " \
                 "{%0,%1,%2,%3},{%4,%5,%6,%7},{%8,%9},{%0,%1,%2,%3};" \
                 : "+r"((d)[0]), "+r"((d)[1]), "+r"((d)[2]), "+r"((d)[3]) \
                 : "r"(a0), "r"(a1), "r"(a2), "r"(a3), "r"(b0), "r"(b1))

// ---------------------------------------------------------------------------
// Kernel prep: block w = cin rows [w*32, w*32+32). Binarize to s8 +/-1 and
// accumulate |k| partials.
__global__ void prep_k1(const float* __restrict__ k) {
    int w = blockIdx.x, co = threadIdx.x;
    const float* base = k + (size_t)w * 32 * COUT + co;
    float s = 0.f;
#pragma unroll
    for (int b = 0; b < 32; b++) {
        float v = base[(size_t)b * COUT];
        g_k8[(size_t)co * KTOT + w * 32 + b] = (v > 0.f) ? 1 : -1;
        s += fabsf(v);
    }
    g_kpart[w * COUT + co] = s;
}
__global__ void prep_k2() {
    int co = threadIdx.x;
    float s = 0.f;
#pragma unroll
    for (int w = 0; w < 72; w++) s += g_kpart[w * COUT + co];
    g_alpha[co] = s * (1.f / (float)(9 * C_));
}

// Binarize padded x to s8 +/-1 + per-pixel sum|x|. Warp per padded pixel.
__global__ void prep_x(const float* __restrict__ x) {
    int pix  = blockIdx.x * 8 + (threadIdx.x >> 5);
    int lane = threadIdx.x & 31;
    if (pix >= NPIXP) return;
    int n  = pix / (HP * WP);
    int r  = pix % (HP * WP);
    int hp = r / WP, wp = r % WP;
    int8_t* dst = g_x8 + (size_t)pix * C_ + lane * 8;
    if (hp >= 1 && hp <= H_ && wp >= 1 && wp <= W_) {
        const float* xp = x + (((size_t)n * H_ + (hp - 1)) * W_ + (wp - 1)) * C_ + lane * 8;
        float4 a = *(const float4*)xp;
        float4 b = *(const float4*)(xp + 4);
        float asum = fabsf(a.x) + fabsf(a.y) + fabsf(a.z) + fabsf(a.w)
                   + fabsf(b.x) + fabsf(b.y) + fabsf(b.z) + fabsf(b.w);
        uint32_t lo = (a.x > 0.f ? 0x01u : 0xFFu)
                    | ((a.y > 0.f ? 0x01u : 0xFFu) << 8)
                    | ((a.z > 0.f ? 0x01u : 0xFFu) << 16)
                    | ((a.w > 0.f ? 0x01u : 0xFFu) << 24);
        uint32_t hi = (b.x > 0.f ? 0x01u : 0xFFu)
                    | ((b.y > 0.f ? 0x01u : 0xFFu) << 8)
                    | ((b.z > 0.f ? 0x01u : 0xFFu) << 16)
                    | ((b.w > 0.f ? 0x01u : 0xFFu) << 24);
        *(uint2*)dst = make_uint2(lo, hi);
#pragma unroll
        for (int o = 16; o; o >>= 1) asum += __shfl_xor_sync(0xffffffffu, asum, o);
        if (lane == 0) g_betap[pix] = asum;
    } else {
        *(uint2*)dst = make_uint2(0xFFFFFFFFu, 0xFFFFFFFFu);
        if (lane == 0) g_betap[pix] = 0.f;
    }
}

// ---------------------------------------------------------------------------
// IMMA implicit-GEMM main. CTA: M=128 pixels (2 h-rows x 64 slots, 8 waste)
// x N=256 couts, K=2304 in 36 chunks of 64. 16 warps as 4(M)x4(N), warp tile
// 32x64, s32 accumulators in registers. cp.async double buffer.
__global__ void __launch_bounds__(512, 1) imma_main(
        const float* __restrict__ bias, float* __restrict__ out) {
    extern __shared__ __align__(128) uint8_t smem[];
    const uint32_t sb = smem_u32(smem);
    float* s_ksc = (float*)(smem + SM_KSC);

    const int tid  = threadIdx.x;
    const int lane = tid & 31;
    const int wid  = tid >> 5;
    const int wm   = wid >> 2;        // 0..3 : M
    const int wn   = wid & 3;         // 0..3 : N
    const int bx   = blockIdx.x;
    const int n    = bx / 28;
    const int h0   = (bx % 28) * 2;

    // ksc per output row m (3x3 window sum of betap / 2304)
    if (tid < 128) {
        int mh = tid >> 6, ww = tid & 63;
        float v = 0.f;
        if (ww < W_) {
            const float* bp = g_betap + (size_t)(n * HP + h0 + mh) * WP + ww;
            float s9 = 0.f;
#pragma unroll
            for (int q = 0; q < 3; q++)
                s9 += bp[q * WP] + bp[q * WP + 1] + bp[q * WP + 2];
            v = s9 * (1.f / 2304.f);
        }
        s_ksc[tid] = v;
    }

    // per-thread cp.async source decomposition
    const int crow = tid >> 2, cseg = tid & 3;        // A: row 0..127, 16B seg
    const int cmh = crow >> 6, cww = crow & 63;

    // ldmatrix lane address offsets (within stage)
    uint32_t aOff[2];
#pragma unroll
    for (int mf = 0; mf < 2; mf++) {
        int row = wm * 32 + mf * 16 + (lane & 7) + ((lane >> 3) & 1) * 8;
        aOff[mf] = row * ASTRIDE + (lane >> 4) * 16;
    }
    uint32_t bOff[8];
#pragma unroll
    for (int nf = 0; nf < 8; nf++) {
        int col = wn * 64 + nf * 8 + (lane & 7);
        bOff[nf] = A_BYTES + col * ASTRIDE + ((lane >> 3) & 1) * 16;
    }

    int acc[2][8][4];
#pragma unroll
    for (int mf = 0; mf < 2; mf++)
#pragma unroll
        for (int nf = 0; nf < 8; nf++)
#pragma unroll
            for (int j = 0; j < 4; j++) acc[mf][nf][j] = 0;

    // prefetch chunk 0
    {
        const int tap = 0, kh = 0, kw = 0, cin0 = 0;
        const int8_t* asrc = g_x8
            + ((size_t)((n * HP + h0 + cmh + kh) * WP + cww + kw)) * C_ + cin0 + cseg * 16;
        CP_ASYNC16(sb + crow * ASTRIDE + cseg * 16, asrc);
#pragma unroll
        for (int i = 0; i < 2; i++) {
            int r2 = crow + i * 128;
            const int8_t* bsrc = g_k8 + (size_t)r2 * KTOT + 0 + cseg * 16;
            CP_ASYNC16(sb + A_BYTES + r2 * ASTRIDE + cseg * 16, bsrc);
        }
        CP_COMMIT();
    }

    for (int c = 0; c < NCHUNK; c++) {
        if (c + 1 < NCHUNK) {
            const int c1 = c + 1;
            const int tap = c1 >> 2, cin0 = (c1 & 3) * 64;
            const int kh = tap / 3, kw = tap - kh * 3;
            const uint32_t stg = ((uint32_t)(c1 & 1)) * STAGE;
            const int8_t* asrc = g_x8
                + ((size_t)((n * HP + h0 + cmh + kh) * WP + cww + kw)) * C_ + cin0 + cseg * 16;
            CP_ASYNC16(sb + stg + crow * ASTRIDE + cseg * 16, asrc);
#pragma unroll
            for (int i = 0; i < 2; i++) {
                int r2 = crow + i * 128;
                const int8_t* bsrc = g_k8 + (size_t)r2 * KTOT + c1 * 64 + cseg * 16;
                CP_ASYNC16(sb + stg + A_BYTES + r2 * ASTRIDE + cseg * 16, bsrc);
            }
            CP_COMMIT();
            CP_WAIT1();
        } else {
            CP_WAIT0();
        }
        __syncthreads();

        const uint32_t stg = ((uint32_t)(c & 1)) * STAGE;
#pragma unroll
        for (int ks = 0; ks < 2; ks++) {
            uint32_t a0[4], a1[4];
            LDSM_X4(a0[0], a0[1], a0[2], a0[3], sb + stg + aOff[0] + ks * 32);
            LDSM_X4(a1[0], a1[1], a1[2], a1[3], sb + stg + aOff[1] + ks * 32);
#pragma unroll
            for (int nf = 0; nf < 8; nf++) {
                uint32_t b0, b1;
                LDSM_X2(b0, b1, sb + stg + bOff[nf] + ks * 32);
                IMMA(acc[0][nf], a0[0], a0[1], a0[2], a0[3], b0, b1);
                IMMA(acc[1][nf], a1[0], a1[1], a1[2], a1[3], b0, b1);
            }
        }
        __syncthreads();
    }

    // Epilogue: out = dot * ksc[m] * alpha[c] + bias[c]
#pragma unroll
    for (int nf = 0; nf < 8; nf++) {
        const int c0 = wn * 64 + nf * 8 + (lane & 3) * 2;
        const float2 al = *(const float2*)(g_alpha + c0);
        const float2 bi = *(const float2*)(bias + c0);
#pragma unroll
        for (int mf = 0; mf < 2; mf++) {
#pragma unroll
            for (int half = 0; half < 2; half++) {
                int r = wm * 32 + mf * 16 + (lane >> 2) + half * 8;
                int ww = r & 63;
                if (ww < W_) {
                    int h = h0 + (r >> 6);
                    float ks = s_ksc[r];
                    float d0 = (float)acc[mf][nf][half * 2 + 0];
                    float d1 = (float)acc[mf][nf][half * 2 + 1];
                    float2 o;
                    o.x = d0 * (ks * al.x) + bi.x;
                    o.y = d1 * (ks * al.y) + bi.y;
                    *(float2*)(out + (((size_t)(n * H_ + h)) * W_ + ww) * COUT + c0) = o;
                }
            }
        }
    }
}

// ---------------------------------------------------------------------------
extern "C" void kernel_launch(void* const* d_in, const int* in_sizes, int n_in,
                              void* d_out, int out_size) {
    (void)in_sizes; (void)n_in; (void)out_size;
    const float* x    = (const float*)d_in[0];
    const float* kern = (const float*)d_in[1];
    const float* bias = (const float*)d_in[2];
    float*       out  = (float*)d_out;

    prep_k1<<<72, 256>>>(kern);
    prep_k2<<<1, 256>>>();
    prep_x<<<NPIXP / 8, 256>>>(x);

    cudaFuncSetAttribute(imma_main, cudaFuncAttributeMaxDynamicSharedMemorySize,
                         SMEM_SZ);
    imma_main<<<N_ * 28, 512, SMEM_SZ>>>(bias, out);
}

// round 6
// speedup vs baseline: 2.6133x; 2.6133x over previous
#include <cuda_runtime.h>
#include <stdint.h>

#define N_   32
#define H_   56
#define W_   56
#define C_   256
#define HP   58          /* padded height */
#define WP   58          /* padded width (logical) */
#define WPS  64          /* padded row stride in words (aligned) */
#define COUT 256
#define NTAP 9
#define NWRD 72          /* 9 taps * 8 cin-groups */
#define NXP  (N_ * HP * WPS)        /* words per bit-plane = 118784 */
#define NTILES (N_ * H_ * 7)        /* 8-pixel tiles = 12544 */
#define NGRP  (NTILES / 8)          /* warp-groups of 8 tiles = 1568 */

// Scratch (device globals — no allocation allowed)
__device__ uint32_t g_kbits[NWRD * COUT];   // [tap*8+gc][cout] packed kernel sign bits
__device__ float    g_kpart[NWRD * COUT];   // partial |k| sums
__device__ float    g_alpha[COUT];          // mean |k| per cout
__device__ uint32_t g_xbt [8 * NXP];        // PLANAR packed x sign bits: [gc][padded pix]
__device__ float    g_betap[NXP];           // sum |x| over channels per padded pixel

// ---------------------------------------------------------------------------
// Coalesced kernel prep: block w handles cin rows [w*32, w*32+32) of the
// (2304 x 256) HWIO kernel matrix -> bits of kbits word w; also |k| partials.
__global__ void prep_k1(const float* __restrict__ k) {
    int w  = blockIdx.x;        // 0..71
    int co = threadIdx.x;       // 0..255
    const float* base = k + (size_t)w * 32 * COUT + co;
    uint32_t bits = 0;
    float s = 0.f;
#pragma unroll
    for (int b = 0; b < 32; b++) {
        float v = base[(size_t)b * COUT];
        if (v > 0.f) bits |= (1u << b);
        s += fabsf(v);
    }
    g_kbits[w * COUT + co] = bits;
    g_kpart[w * COUT + co] = s;
}

__global__ void prep_k2() {
    int co = threadIdx.x;
    float s = 0.f;
#pragma unroll
    for (int w = 0; w < NWRD; w++) s += g_kpart[w * COUT + co];
    g_alpha[co] = s * (1.f / (NTAP * C_));
}

// ---------------------------------------------------------------------------
// Pack input sign bits (planar layout) + per-pixel sum|x|.
// One warp per padded pixel; border ring -> bits 0 (sign -1) and beta 0.
__global__ void prep_x(const float* __restrict__ x) {
    int pix  = blockIdx.x * 8 + (threadIdx.x >> 5);
    int lane = threadIdx.x & 31;
    if (pix >= N_ * HP * WP) return;
    int n  = pix / (HP * WP);
    int r  = pix % (HP * WP);
    int hp = r / WP, wp = r % WP;
    int ppos = (n * HP + hp) * WPS + wp;
    if (hp >= 1 && hp <= H_ && wp >= 1 && wp <= W_) {
        const float* xp = x + (((size_t)n * H_ + (hp - 1)) * W_ + (wp - 1)) * C_;
        float asum = 0.f;
        uint32_t bm[8];
#pragma unroll
        for (int j = 0; j < 8; j++) {
            float v = xp[j * 32 + lane];
            bm[j] = __ballot_sync(0xffffffffu, v > 0.f);
            asum += fabsf(v);
        }
#pragma unroll
        for (int o = 16; o; o >>= 1) asum += __shfl_xor_sync(0xffffffffu, asum, o);
#pragma unroll
        for (int j = 0; j < 8; j++)
            if (lane == j) g_xbt[(size_t)j * NXP + ppos] = bm[j];
        if (lane == 0) g_betap[ppos] = asum;
    } else {
        if (lane < 8) g_xbt[(size_t)lane * NXP + ppos] = 0u;
        if (lane == 0) g_betap[ppos] = 0.f;
    }
}

// ---------------------------------------------------------------------------
// Main XNOR-popcount conv with kw-level carry-save adder.
// popc(t0)+popc(t1)+popc(t2) = popc(t0^t1^t2) + 2*popc(maj(t0,t1,t2))
// -> 4 POPC instead of 6 per p-step per cout pair (POPC pipe is the binder).
// blockIdx.y = cout-group cg (64 couts). Warp = 8 pixels x 64 couts.
__global__ void __launch_bounds__(256, 4) binconv_main(
        const float* __restrict__ bias, float* __restrict__ out) {
    extern __shared__ uint32_t s_k[];   // NWRD * 64 words = 18KB slice

    const int cg = blockIdx.y;
    {   // cooperative vectorized smem fill of this cg's slice
        const uint4* src = (const uint4*)g_kbits;
        uint4*       dst = (uint4*)s_k;
        for (int m = threadIdx.x; m < NWRD * 16; m += 256) {
            int w = m >> 4, j = m & 15;
            dst[m] = src[w * 64 + cg * 16 + j];
        }
    }
    __syncthreads();

    const int warp = threadIdx.x >> 5;
    const int lane = threadIdx.x & 31;
    const int co0  = cg * 64 + 2 * lane;

    const float2 al = *(const float2*)(g_alpha + co0);
    const float2 bi = *(const float2*)(bias + co0);

    for (int grp = blockIdx.x; grp < NGRP; grp += gridDim.x) {
        int t  = grp * 8 + warp;
        int tw = t % 7;
        int tr = t / 7;
        int th = tr % H_;
        int n  = tr / H_;
        int rb = (n * HP + th) * WPS + tw * 8;   // padded base: row th, col tw*8

        // packed 16-bit accumulators: lo16 = co0, hi16 = co0+1
        uint32_t accS[8] = {0,0,0,0,0,0,0,0};    // weight-1 popcounts (<= 768)
        uint32_t accM[8] = {0,0,0,0,0,0,0,0};    // weight-2 popcounts (<= 768)

#pragma unroll 2
        for (int gc = 0; gc < 8; gc++) {
            const uint32_t* xplane = g_xbt + (size_t)gc * NXP + rb;
#pragma unroll
            for (int kh = 0; kh < 3; kh++) {
                const uint4* xr = (const uint4*)(xplane + kh * WPS);
                uint4 q0 = xr[0], q1 = xr[1], q2 = xr[2];
                uint32_t xw[12] = {q0.x, q0.y, q0.z, q0.w,
                                   q1.x, q1.y, q1.z, q1.w,
                                   q2.x, q2.y, q2.z, q2.w};
                const uint2* k0 = (const uint2*)(s_k + ((kh * 3 + 0) * 8 + gc) * 64);
                const uint2* k1 = (const uint2*)(s_k + ((kh * 3 + 1) * 8 + gc) * 64);
                const uint2* k2 = (const uint2*)(s_k + ((kh * 3 + 2) * 8 + gc) * 64);
                uint2 kv0 = k0[lane], kv1 = k1[lane], kv2 = k2[lane];
#pragma unroll
                for (int p = 0; p < 8; p++) {
                    uint32_t t0 = xw[p] ^ kv0.x;
                    uint32_t t1 = xw[p + 1] ^ kv1.x;
                    uint32_t t2 = xw[p + 2] ^ kv2.x;
                    uint32_t s0 = t0 ^ t1 ^ t2;                    // LOP3 0x96
                    uint32_t m0 = (t0 & t1) | (t0 & t2) | (t1 & t2); // LOP3 0xE8
                    uint32_t u0 = xw[p] ^ kv0.y;
                    uint32_t u1 = xw[p + 1] ^ kv1.y;
                    uint32_t u2 = xw[p + 2] ^ kv2.y;
                    uint32_t s1 = u0 ^ u1 ^ u2;
                    uint32_t m1 = (u0 & u1) | (u0 & u2) | (u1 & u2);
                    accS[p] += (uint32_t)__popc(s0) + ((uint32_t)__popc(s1) << 16);
                    accM[p] += (uint32_t)__popc(m0) + ((uint32_t)__popc(m1) << 16);
                }
            }
        }

        // Epilogue: ksum[p] = 3x3 window sum of beta; out = dot*K*alpha + bias
        const float* bp = g_betap + rb;
        float rs[10];
        {
            float4 a = *(const float4*)(bp);
            float4 b = *(const float4*)(bp + WPS);
            float4 c = *(const float4*)(bp + 2 * WPS);
            rs[0] = a.x + b.x + c.x;  rs[1] = a.y + b.y + c.y;
            rs[2] = a.z + b.z + c.z;  rs[3] = a.w + b.w + c.w;
        }
        {
            float4 a = *(const float4*)(bp + 4);
            float4 b = *(const float4*)(bp + WPS + 4);
            float4 c = *(const float4*)(bp + 2 * WPS + 4);
            rs[4] = a.x + b.x + c.x;  rs[5] = a.y + b.y + c.y;
            rs[6] = a.z + b.z + c.z;  rs[7] = a.w + b.w + c.w;
        }
        {
            float2 a = *(const float2*)(bp + 8);
            float2 b = *(const float2*)(bp + WPS + 8);
            float2 c = *(const float2*)(bp + 2 * WPS + 8);
            rs[8] = a.x + b.x + c.x;  rs[9] = a.y + b.y + c.y;
        }

        // linear out pixel index = t*8 + p  (W_ = 7 tiles * 8)
        float* op = out + (size_t)t * 8 * COUT + co0;
#pragma unroll
        for (int p = 0; p < 8; p++) {
            float ks = (rs[p] + rs[p + 1] + rs[p + 2]) * (1.f / 2304.f);
            uint32_t T0 = (accS[p] & 0xFFFFu) + 2u * (accM[p] & 0xFFFFu);
            uint32_t T1 = (accS[p] >> 16)     + 2u * (accM[p] >> 16);
            float d0 = 2304.f - 2.f * (float)T0;
            float d1 = 2304.f - 2.f * (float)T1;
            float2 o;
            o.x = d0 * (ks * al.x) + bi.x;
            o.y = d1 * (ks * al.y) + bi.y;
            *(float2*)(op + (size_t)p * COUT) = o;
        }
    }
}

// ---------------------------------------------------------------------------
extern "C" void kernel_launch(void* const* d_in, const int* in_sizes, int n_in,
                              void* d_out, int out_size) {
    (void)in_sizes; (void)n_in; (void)out_size;
    const float* x    = (const float*)d_in[0];
    const float* kern = (const float*)d_in[1];
    const float* bias = (const float*)d_in[2];
    float*       out  = (float*)d_out;

    prep_k1<<<NWRD, 256>>>(kern);
    prep_k2<<<1, 256>>>();

    const int npixp = N_ * HP * WP;           // 107648, divisible by 8
    prep_x<<<npixp / 8, 256>>>(x);

    const size_t smem_bytes = (size_t)NWRD * 64 * 4;   // 18432
    dim3 grid(185, 4);
    binconv_main<<<grid, 256, smem_bytes>>>(bias, out);
}